// round 16
// baseline (speedup 1.0000x reference)
#include <cuda_runtime.h>
#include <cuda_fp16.h>
#include <math.h>
#include <stdint.h>
#include <stddef.h>

#define B_ 2
#define T_ 2048
#define C_ 1024
#define H_ 16
#define HD_ 64
#define M_ (B_*T_)

// ---------------- scratch ----------------
__device__ float  g_qkv[(size_t)M_ * 3 * C_];          // fp32 qkv (pre-rope)
__device__ float  g_x1[(size_t)M_ * C_];               // fp32 residual stream
__device__ float2 g_rope[(size_t)T_ * 32];             // (cos,sin) per (t,i)
__device__ __half g_hh[(size_t)M_ * C_];               // rmsnorm output
__device__ __half g_wh[(size_t)16 * C_ * C_];          // all weights fp16
__device__ __half g_qh[(size_t)B_ * H_ * T_ * HD_];
__device__ __half g_kh[(size_t)B_ * H_ * T_ * HD_];
__device__ __half g_vh[(size_t)B_ * H_ * T_ * HD_];
__device__ __half g_attnh[(size_t)M_ * C_];
__device__ __half g_uvh[(size_t)M_ * 8 * C_];
__device__ __half g_gatedh[(size_t)M_ * 4 * C_];

// weight offsets inside g_wh (in elements)
#define WOFF_QKV 0
#define WOFF_OUT ((size_t)3 * C_ * C_)
#define WOFF_UV  ((size_t)4 * C_ * C_)
#define WOFF_MLP ((size_t)12 * C_ * C_)

// ---------------- helpers ----------------
__device__ __forceinline__ uint32_t smem_u32(const void* p) {
    uint32_t a;
    asm("{ .reg .u64 t; cvta.to.shared.u64 t, %1; cvt.u32.u64 %0, t; }" : "=r"(a) : "l"(p));
    return a;
}
// fp16 m16n8k16, fp32 accumulate
__device__ __forceinline__ void mma_f16(float* c, const uint32_t* a, const uint32_t* b) {
    asm volatile("mma.sync.aligned.m16n8k16.row.col.f32.f16.f16.f32 "
                 "{%0,%1,%2,%3}, {%4,%5,%6,%7}, {%8,%9}, {%0,%1,%2,%3};"
                 : "+f"(c[0]), "+f"(c[1]), "+f"(c[2]), "+f"(c[3])
                 : "r"(a[0]), "r"(a[1]), "r"(a[2]), "r"(a[3]), "r"(b[0]), "r"(b[1]));
}
__device__ __forceinline__ void ldmatrix_x4(uint32_t& r0, uint32_t& r1, uint32_t& r2, uint32_t& r3,
                                            uint32_t addr) {
    asm volatile("ldmatrix.sync.aligned.m8n8.x4.shared.b16 {%0,%1,%2,%3}, [%4];"
                 : "=r"(r0), "=r"(r1), "=r"(r2), "=r"(r3) : "r"(addr));
}
__device__ __forceinline__ float fsqrt_approx(float x) {
    float r;
    asm("sqrt.approx.f32 %0, %1;" : "=f"(r) : "f"(x));
    return r;
}

// ---------------- rope table: (t,i) -> (cos, sin), double precision (matches reference) ----------------
__global__ __launch_bounds__(256)
void rope_table_kernel()
{
    const int gid = blockIdx.x * 256 + threadIdx.x;   // T_*32
    const int i = gid & 31, t = gid >> 5;
    const double invf = pow(10000.0, -((double)(2 * i)) / 64.0);
    double ds, dc;
    sincos((double)t * invf, &ds, &dc);
    g_rope[gid] = make_float2((float)dc, (float)ds);
}

// ---------------- weight conversion: fp32 -> fp16, all 4 matrices ----------------
__global__ __launch_bounds__(256)
void wconv_kernel(const float* __restrict__ w_qkv, const float* __restrict__ w_out,
                  const float* __restrict__ w_uv, const float* __restrict__ w_mlp)
{
    const size_t gid = (size_t)blockIdx.x * 256 + threadIdx.x;   // over 16C^2/4
    const size_t e = gid * 4;
    const float* src;
    size_t off;
    if (e < WOFF_OUT)      { src = w_qkv; off = e; }
    else if (e < WOFF_UV)  { src = w_out; off = e - WOFF_OUT; }
    else if (e < WOFF_MLP) { src = w_uv;  off = e - WOFF_UV; }
    else                   { src = w_mlp; off = e - WOFF_MLP; }
    float4 v = *reinterpret_cast<const float4*>(src + off);
    __half2 h0 = __floats2half2_rn(v.x, v.y);
    __half2 h1 = __floats2half2_rn(v.z, v.w);
    uint2 p; p.x = *reinterpret_cast<uint32_t*>(&h0); p.y = *reinterpret_cast<uint32_t*>(&h1);
    *reinterpret_cast<uint2*>(g_wh + e) = p;
}

// ---------------- fp16 tensor-core GEMM: C[M,N] = A[M,K] @ W[N,K]^T (+bias)(+res) ----------------
#define HP 40

__global__ __launch_bounds__(256)
void tgemm_kernel(const __half* __restrict__ A, const __half* __restrict__ W,
                  const float* __restrict__ bias, const float* __restrict__ res,
                  float* __restrict__ Cf, __half* __restrict__ Ch, int M, int N, int K)
{
    __shared__ __half As[128][HP];
    __shared__ __half Bs[128][HP];
    const int tid = threadIdx.x;
    const int lane = tid & 31, warp = tid >> 5;
    const int bm = blockIdx.y * 128, bn = blockIdx.x * 128;
    const int wm = (warp & 3) * 32;
    const int wn = (warp >> 2) * 64;
    const int grp = lane >> 2, four = lane & 3;
    const int lr = tid >> 3, lq = (tid & 7) << 2;

    const uint32_t a_base = smem_u32(&As[wm + (lane & 15)][(lane >> 4) * 8]);
    uint32_t b_base[4];
#pragma unroll
    for (int ntp = 0; ntp < 4; ntp++)
        b_base[ntp] = smem_u32(&Bs[wn + (2 * ntp + (lane >> 4)) * 8 + (lane & 7)][((lane >> 3) & 1) * 8]);

    float acc[2][8][4];
#pragma unroll
    for (int mi = 0; mi < 2; mi++)
#pragma unroll
        for (int ni = 0; ni < 8; ni++)
#pragma unroll
            for (int j = 0; j < 4; j++) acc[mi][ni][j] = 0.f;

    for (int k0 = 0; k0 < K; k0 += 32) {
        __syncthreads();
#pragma unroll
        for (int it = 0; it < 4; it++) {
            int r = lr + it * 32;
            uint2 pa = *reinterpret_cast<const uint2*>(&A[(size_t)(bm + r) * K + k0 + lq]);
            *reinterpret_cast<uint2*>(&As[r][lq]) = pa;
            uint2 pw = *reinterpret_cast<const uint2*>(&W[(size_t)(bn + r) * K + k0 + lq]);
            *reinterpret_cast<uint2*>(&Bs[r][lq]) = pw;
        }
        __syncthreads();
#pragma unroll
        for (int ks = 0; ks < 2; ks++) {
            const uint32_t co = (uint32_t)(ks * 16) * 2;
            uint32_t af[2][4], bf[8][2];
#pragma unroll
            for (int mi = 0; mi < 2; mi++)
                ldmatrix_x4(af[mi][0], af[mi][1], af[mi][2], af[mi][3],
                            a_base + (uint32_t)(mi * 16 * HP) * 2 + co);
#pragma unroll
            for (int ntp = 0; ntp < 4; ntp++)
                ldmatrix_x4(bf[2 * ntp][0], bf[2 * ntp][1], bf[2 * ntp + 1][0], bf[2 * ntp + 1][1],
                            b_base[ntp] + co);
#pragma unroll
            for (int mi = 0; mi < 2; mi++)
#pragma unroll
                for (int ni = 0; ni < 8; ni++)
                    mma_f16(acc[mi][ni], af[mi], bf[ni]);
        }
    }

#pragma unroll
    for (int mi = 0; mi < 2; mi++) {
#pragma unroll
        for (int ni = 0; ni < 8; ni++) {
            int row = bm + wm + mi * 16 + grp;
            int col = bn + wn + ni * 8 + 2 * four;
            float bx = 0.f, by = 0.f;
            if (bias) { bx = bias[col]; by = bias[col + 1]; }
#pragma unroll
            for (int half_m = 0; half_m < 2; half_m++) {
                int rr = row + half_m * 8;
                float vx = acc[mi][ni][half_m * 2 + 0] + bx;
                float vy = acc[mi][ni][half_m * 2 + 1] + by;
                if (res) {
                    float2 rv = *reinterpret_cast<const float2*>(&res[(size_t)rr * N + col]);
                    vx += rv.x; vy += rv.y;
                }
                if (Cf) {
                    float2 ov; ov.x = vx; ov.y = vy;
                    *reinterpret_cast<float2*>(&Cf[(size_t)rr * N + col]) = ov;
                } else {
                    __half2 oh = __floats2half2_rn(vx, vy);
                    *reinterpret_cast<__half2*>(&Ch[(size_t)rr * N + col]) = oh;
                }
            }
        }
    }
}

// ---------------- rmsnorm: fp32 in -> fp16 out ----------------
__global__ __launch_bounds__(256)
void rmsnorm_kernel(const float* __restrict__ x, __half* __restrict__ o)
{
    const int row = blockIdx.x;
    const float4* xr = reinterpret_cast<const float4*>(x + (size_t)row * C_);
    float4 v = xr[threadIdx.x];
    float ss = v.x * v.x + v.y * v.y + v.z * v.z + v.w * v.w;
#pragma unroll
    for (int off = 16; off > 0; off >>= 1)
        ss += __shfl_xor_sync(0xffffffffu, ss, off);
    __shared__ float red[8];
    if ((threadIdx.x & 31) == 0) red[threadIdx.x >> 5] = ss;
    __syncthreads();
    float tot = 0.f;
#pragma unroll
    for (int i = 0; i < 8; i++) tot += red[i];
    const float sc = rsqrtf(tot * (1.f / (float)C_) + 1e-6f);
    __half2 h0 = __floats2half2_rn(v.x * sc, v.y * sc);
    __half2 h1 = __floats2half2_rn(v.z * sc, v.w * sc);
    uint2 p; p.x = *reinterpret_cast<uint32_t*>(&h0); p.y = *reinterpret_cast<uint32_t*>(&h1);
    *reinterpret_cast<uint2*>(o + (size_t)row * C_ + threadIdx.x * 4) = p;
}

// ---------------- rope + transpose: table-driven, fp32 qkv -> fp16 q,k,v (B,H,T,HD) ----------------
__global__ __launch_bounds__(256)
void rope_kernel(const float* __restrict__ qkv,
                 __half* __restrict__ q, __half* __restrict__ k, __half* __restrict__ v)
{
    const int gid = blockIdx.x * 256 + threadIdx.x;
    const int i  = gid & 31;
    const int t  = (gid >> 5) & (T_ - 1);
    const int hh = (gid >> 16) & (H_ - 1);
    const int b  = gid >> 20;
    const size_t base = (size_t)(b * T_ + t) * (3 * C_) + hh * HD_;
    const float qx1 = qkv[base + i],            qx2 = qkv[base + i + 32];
    const float kx1 = qkv[base + C_ + i],       kx2 = qkv[base + C_ + i + 32];
    const float vx1 = qkv[base + 2 * C_ + i],   vx2 = qkv[base + 2 * C_ + i + 32];
    const float2 cs = g_rope[t * 32 + i];
    const float c = cs.x, s = cs.y;
    const size_t ob = ((size_t)(b * H_ + hh) * T_ + t) * HD_;
    q[ob + i]      = __float2half_rn( qx1 * c + qx2 * s);
    q[ob + i + 32] = __float2half_rn(-qx1 * s + qx2 * c);
    k[ob + i]      = __float2half_rn( kx1 * c + kx2 * s);
    k[ob + i + 32] = __float2half_rn(-kx1 * s + kx2 * c);
    v[ob + i]      = __float2half_rn(vx1);
    v[ob + i + 32] = __float2half_rn(vx2);
}

// ---------------- FA2-style fp16-mma causal hyperbolic attention (R15, unchanged) ----------------
#define AP 72

struct AttnSmem3 {
    __half Qs[64][AP];    // Q tile in prologue; P tile in mainloop (alias)
    __half Ks[64][AP];
    __half Vt[64][AP];    // [d][key]
    float q0s[64], k0s[64];
};

extern __shared__ char attn_smem_raw[];

__global__ __launch_bounds__(128)
void attn_kernel(const __half* __restrict__ Q, const __half* __restrict__ K,
                 const __half* __restrict__ V, const float* __restrict__ curv,
                 __half* __restrict__ out)
{
    AttnSmem3& sm = *reinterpret_cast<AttnSmem3*>(attn_smem_raw);
    __half (*Ps)[AP] = sm.Qs;
    const int tid = threadIdx.x;
    const int lane = tid & 31, warp = tid >> 5;
    const int grp = lane >> 2, four = lane & 3;
    const int tq = blockIdx.x, h = blockIdx.y, b = blockIdx.z;
    const float kc = curv[h];
    const float sqkc = sqrtf(kc), ikc = 1.0f / kc;
    const size_t bhT = ((size_t)b * H_ + h) * T_;
    const int wrow = warp * 16;
    const float LOG2E = 1.4426950408889634f;

    {
        const __half* Qp = Q + (bhT + (size_t)tq * 64) * HD_;
#pragma unroll
        for (int it = 0; it < 8; it++) {
            int f = tid + it * 128;
            int r = f >> 4, dq = (f & 15) << 2;
            uint2 qv = *reinterpret_cast<const uint2*>(&Qp[r * HD_ + dq]);
            *reinterpret_cast<uint2*>(&sm.Qs[r][dq]) = qv;
        }
    }
    __syncthreads();
    if (tid < 64) {
        float ss = 0.f;
#pragma unroll 8
        for (int d = 0; d < 64; d++) { float qv = __half2float(sm.Qs[tid][d]); ss += qv * qv; }
        sm.q0s[tid] = sqrtf(kc + ss);
    }
    __syncthreads();

    const int r0 = wrow + grp, r1 = wrow + grp + 8;
    uint32_t qf[4][4];
#pragma unroll
    for (int ks = 0; ks < 4; ks++) {
        int kb = ks * 16 + 2 * four;
        qf[ks][0] = *reinterpret_cast<const uint32_t*>(&sm.Qs[r0][kb]);
        qf[ks][1] = *reinterpret_cast<const uint32_t*>(&sm.Qs[r1][kb]);
        qf[ks][2] = *reinterpret_cast<const uint32_t*>(&sm.Qs[r0][kb + 8]);
        qf[ks][3] = *reinterpret_cast<const uint32_t*>(&sm.Qs[r1][kb + 8]);
    }
    const float q0a = sm.q0s[r0];
    const float q0b = sm.q0s[r1];

    float o[8][4];
#pragma unroll
    for (int nt = 0; nt < 8; nt++)
#pragma unroll
        for (int j = 0; j < 4; j++) o[nt][j] = 0.f;
    float m0 = -1e30f, m1 = -1e30f, l0 = 0.f, l1 = 0.f;

    for (int kt = 0; kt <= tq; kt++) {
        __syncthreads();
        const __half* Kp = K + (bhT + (size_t)kt * 64) * HD_;
        const __half* Vp = V + (bhT + (size_t)kt * 64) * HD_;
#pragma unroll
        for (int it = 0; it < 8; it++) {
            int f = tid + it * 128;
            int r = f >> 4, dq = (f & 15) << 2;
            uint2 kv = *reinterpret_cast<const uint2*>(&Kp[r * HD_ + dq]);
            *reinterpret_cast<uint2*>(&sm.Ks[r][dq]) = kv;
            uint2 vv = *reinterpret_cast<const uint2*>(&Vp[r * HD_ + dq]);
            const __half* vh = reinterpret_cast<const __half*>(&vv);
            sm.Vt[dq + 0][r] = vh[0]; sm.Vt[dq + 1][r] = vh[1];
            sm.Vt[dq + 2][r] = vh[2]; sm.Vt[dq + 3][r] = vh[3];
        }
        __syncthreads();
        if (tid < 64) {
            float ss = 0.f;
#pragma unroll 8
            for (int d = 0; d < 64; d++) { float kv = __half2float(sm.Ks[tid][d]); ss += kv * kv; }
            sm.k0s[tid] = sqrtf(kc + ss);
        }
        __syncthreads();

        float s[8][4];
#pragma unroll
        for (int nt = 0; nt < 8; nt++)
#pragma unroll
            for (int j = 0; j < 4; j++) s[nt][j] = 0.f;
#pragma unroll
        for (int ks = 0; ks < 4; ks++) {
            const int kb = ks * 16 + 2 * four;
#pragma unroll
            for (int nt = 0; nt < 8; nt++) {
                uint32_t bf[2];
                bf[0] = *reinterpret_cast<const uint32_t*>(&sm.Ks[nt * 8 + grp][kb]);
                bf[1] = *reinterpret_cast<const uint32_t*>(&sm.Ks[nt * 8 + grp][kb + 8]);
                mma_f16(s[nt], qf[ks], bf);
            }
        }

        const bool diag = (kt == tq);
#pragma unroll
        for (int nt = 0; nt < 8; nt++) {
            const int c0 = nt * 8 + 2 * four;
            const float k00 = sm.k0s[c0], k01 = sm.k0s[c0 + 1];
#pragma unroll
            for (int j = 0; j < 4; j++) {
                const float q0v = (j < 2) ? q0a : q0b;
                const float k0v = (j & 1) ? k01 : k00;
                float z = (q0v * k0v - s[nt][j]) * ikc;
                z = fmaxf(z, 1.000001f);
                float w = fsqrt_approx(z * z - 1.f);
                float dis = sqkc * __logf(z + w);
                s[nt][j] = -dis;
            }
            if (diag) {
                if (c0     > r0) s[nt][0] = -1e30f;
                if (c0 + 1 > r0) s[nt][1] = -1e30f;
                if (c0     > r1) s[nt][2] = -1e30f;
                if (c0 + 1 > r1) s[nt][3] = -1e30f;
            }
        }

        float mx0 = -1e30f, mx1 = -1e30f;
#pragma unroll
        for (int nt = 0; nt < 8; nt++) {
            mx0 = fmaxf(mx0, fmaxf(s[nt][0], s[nt][1]));
            mx1 = fmaxf(mx1, fmaxf(s[nt][2], s[nt][3]));
        }
        mx0 = fmaxf(mx0, __shfl_xor_sync(0xffffffffu, mx0, 1));
        mx0 = fmaxf(mx0, __shfl_xor_sync(0xffffffffu, mx0, 2));
        mx1 = fmaxf(mx1, __shfl_xor_sync(0xffffffffu, mx1, 1));
        mx1 = fmaxf(mx1, __shfl_xor_sync(0xffffffffu, mx1, 2));
        const float nm0 = fmaxf(m0, mx0), nm1 = fmaxf(m1, mx1);
        const float a0 = __expf(m0 - nm0), a1 = __expf(m1 - nm1);
        float rs0 = 0.f, rs1 = 0.f;
        __half2 ph[8][2];
#pragma unroll
        for (int nt = 0; nt < 8; nt++) {
            float p0 = exp2f((s[nt][0] - nm0) * LOG2E);
            float p1 = exp2f((s[nt][1] - nm0) * LOG2E);
            float p2 = exp2f((s[nt][2] - nm1) * LOG2E);
            float p3 = exp2f((s[nt][3] - nm1) * LOG2E);
            ph[nt][0] = __floats2half2_rn(p0, p1);
            ph[nt][1] = __floats2half2_rn(p2, p3);
            float2 f0 = __half22float2(ph[nt][0]);
            float2 f1 = __half22float2(ph[nt][1]);
            rs0 += f0.x + f0.y; rs1 += f1.x + f1.y;
        }
        rs0 += __shfl_xor_sync(0xffffffffu, rs0, 1);
        rs0 += __shfl_xor_sync(0xffffffffu, rs0, 2);
        rs1 += __shfl_xor_sync(0xffffffffu, rs1, 1);
        rs1 += __shfl_xor_sync(0xffffffffu, rs1, 2);
        l0 = l0 * a0 + rs0; l1 = l1 * a1 + rs1;
        m0 = nm0; m1 = nm1;

#pragma unroll
        for (int nt = 0; nt < 8; nt++) {
            o[nt][0] *= a0; o[nt][1] *= a0; o[nt][2] *= a1; o[nt][3] *= a1;
            const int c0 = nt * 8 + 2 * four;
            *reinterpret_cast<__half2*>(&Ps[r0][c0]) = ph[nt][0];
            *reinterpret_cast<__half2*>(&Ps[r1][c0]) = ph[nt][1];
        }
        __syncwarp();

#pragma unroll
        for (int ks = 0; ks < 4; ks++) {
            const int kb = ks * 16 + 2 * four;
            uint32_t af[4];
            af[0] = *reinterpret_cast<const uint32_t*>(&Ps[r0][kb]);
            af[1] = *reinterpret_cast<const uint32_t*>(&Ps[r1][kb]);
            af[2] = *reinterpret_cast<const uint32_t*>(&Ps[r0][kb + 8]);
            af[3] = *reinterpret_cast<const uint32_t*>(&Ps[r1][kb + 8]);
#pragma unroll
            for (int nt = 0; nt < 8; nt++) {
                uint32_t bf[2];
                bf[0] = *reinterpret_cast<const uint32_t*>(&sm.Vt[nt * 8 + grp][kb]);
                bf[1] = *reinterpret_cast<const uint32_t*>(&sm.Vt[nt * 8 + grp][kb + 8]);
                mma_f16(o[nt], af, bf);
            }
        }
    }

    const float inv0 = 1.f / l0, inv1 = 1.f / l1;
    const int gr0 = tq * 64 + r0, gr1 = tq * 64 + r1;
#pragma unroll
    for (int nt = 0; nt < 8; nt++) {
        const int d0 = nt * 8 + 2 * four;
        __half2 ov;
        ov = __floats2half2_rn(o[nt][0] * inv0, o[nt][1] * inv0);
        *reinterpret_cast<__half2*>(&out[(((size_t)b * T_ + gr0) * H_ + h) * HD_ + d0]) = ov;
        ov = __floats2half2_rn(o[nt][2] * inv1, o[nt][3] * inv1);
        *reinterpret_cast<__half2*>(&out[(((size_t)b * T_ + gr1) * H_ + h) * HD_ + d0]) = ov;
    }
}

// ---------------- gating: g = u * silu(vg), fp16 in/out ----------------
__global__ __launch_bounds__(256)
void gate_kernel(const __half* __restrict__ uv, __half* __restrict__ g)
{
    const size_t gid = (size_t)blockIdx.x * 256 + threadIdx.x;
    const size_t row = gid >> 10;
    const size_t c4 = gid & 1023;
    uint2 pu = *reinterpret_cast<const uint2*>(uv + row * (8 * (size_t)C_) + c4 * 4);
    uint2 pv = *reinterpret_cast<const uint2*>(uv + row * (8 * (size_t)C_) + 4 * C_ + c4 * 4);
    const __half* uh = reinterpret_cast<const __half*>(&pu);
    const __half* vh = reinterpret_cast<const __half*>(&pv);
    __half rh[4];
#pragma unroll
    for (int j = 0; j < 4; j++) {
        float u = __half2float(uh[j]);
        float vg = __half2float(vh[j]);
        rh[j] = __float2half_rn(u * vg / (1.f + __expf(-vg)));
    }
    *reinterpret_cast<uint2*>(g + gid * 4) = *reinterpret_cast<uint2*>(rh);
}

// ---------------- launch ----------------
extern "C" void kernel_launch(void* const* d_in, const int* in_sizes, int n_in,
                              void* d_out, int out_size)
{
    const float* x      = (const float*)d_in[0];
    const float* w_qkv  = (const float*)d_in[1];
    const float* w_out  = (const float*)d_in[2];
    const float* curv   = (const float*)d_in[3];
    const float* w_uv   = (const float*)d_in[4];
    const float* b_uv   = (const float*)d_in[5];
    const float* w_mlp  = (const float*)d_in[6];
    const float* b_mlp  = (const float*)d_in[7];
    float* out = (float*)d_out;

    float *qkv, *x1;
    __half *hh, *wh, *qh, *kh, *vh, *attnh, *uvh, *gatedh;
    cudaGetSymbolAddress((void**)&qkv, g_qkv);
    cudaGetSymbolAddress((void**)&x1, g_x1);
    cudaGetSymbolAddress((void**)&hh, g_hh);
    cudaGetSymbolAddress((void**)&wh, g_wh);
    cudaGetSymbolAddress((void**)&qh, g_qh);
    cudaGetSymbolAddress((void**)&kh, g_kh);
    cudaGetSymbolAddress((void**)&vh, g_vh);
    cudaGetSymbolAddress((void**)&attnh, g_attnh);
    cudaGetSymbolAddress((void**)&uvh, g_uvh);
    cudaGetSymbolAddress((void**)&gatedh, g_gatedh);

    const int attn_smem = (int)sizeof(AttnSmem3);
    cudaFuncSetAttribute(attn_kernel, cudaFuncAttributeMaxDynamicSharedMemorySize, attn_smem);

    // 0a) rope table (FP64 trig, 16x fewer threads than fused version)
    rope_table_kernel<<<(T_ * 32) / 256, 256>>>();
    // 0b) convert all weights to fp16
    wconv_kernel<<<(16 * C_ * C_ / 4) / 256, 256>>>(w_qkv, w_out, w_uv, w_mlp);
    // 1) h = rmsnorm(x) -> fp16
    rmsnorm_kernel<<<M_, 256>>>(x, hh);
    // 2) qkv = h @ w_qkv^T  (fp32 out)
    tgemm_kernel<<<dim3(3 * C_ / 128, M_ / 128), 256>>>(hh, wh + WOFF_QKV, nullptr, nullptr, qkv, nullptr, M_, 3 * C_, C_);
    // 3) rope (table-driven) -> fp16 q,k,v
    rope_kernel<<<(B_ * H_ * T_ * 32) / 256, 256>>>(qkv, qh, kh, vh);
    // 4) attention (fp16 mma) -> fp16 attn
    attn_kernel<<<dim3(T_ / 64, H_, B_), 128, attn_smem>>>(qh, kh, vh, curv, attnh);
    // 5) x1 = x + attn @ w_out^T  (fp32 out)
    tgemm_kernel<<<dim3(C_ / 128, M_ / 128), 256>>>(attnh, wh + WOFF_OUT, nullptr, x, x1, nullptr, M_, C_, C_);
    // 6) h = rmsnorm(x1) -> fp16
    rmsnorm_kernel<<<M_, 256>>>(x1, hh);
    // 7) uv = h @ w_uv^T + b_uv  (fp16 out)
    tgemm_kernel<<<dim3(8 * C_ / 128, M_ / 128), 256>>>(hh, wh + WOFF_UV, b_uv, nullptr, nullptr, uvh, M_, 8 * C_, C_);
    // 8) gated = u * silu(vg)  (fp16)
    gate_kernel<<<(M_ * 4 * C_ / 4) / 256, 256>>>(uvh, gatedh);
    // 9) out = x1 + gated @ w_mlp^T + b_mlp  (fp32 out)
    tgemm_kernel<<<dim3(C_ / 128, M_ / 128), 256>>>(gatedh, wh + WOFF_MLP, b_mlp, x1, out, nullptr, M_, C_, 4 * C_);
}

// round 17
// speedup vs baseline: 1.6710x; 1.6710x over previous
#include <cuda_runtime.h>
#include <cuda_fp16.h>
#include <math.h>
#include <stdint.h>
#include <stddef.h>

#define B_ 2
#define T_ 2048
#define C_ 1024
#define H_ 16
#define HD_ 64
#define M_ (B_*T_)

// ---------------- scratch ----------------
__device__ float  g_qkv[(size_t)M_ * 3 * C_];
__device__ float  g_x1[(size_t)M_ * C_];
__device__ float2 g_rope[(size_t)T_ * 32];
__device__ __half g_hh[(size_t)M_ * C_];
__device__ __half g_wh[(size_t)16 * C_ * C_];
__device__ __half g_qh[(size_t)B_ * H_ * T_ * HD_];
__device__ __half g_kh[(size_t)B_ * H_ * T_ * HD_];
__device__ __half g_vh[(size_t)B_ * H_ * T_ * HD_];
__device__ __half g_attnh[(size_t)M_ * C_];
__device__ __half g_uvh[(size_t)M_ * 8 * C_];
__device__ __half g_gatedh[(size_t)M_ * 4 * C_];

#define WOFF_QKV 0
#define WOFF_OUT ((size_t)3 * C_ * C_)
#define WOFF_UV  ((size_t)4 * C_ * C_)
#define WOFF_MLP ((size_t)12 * C_ * C_)

// ---------------- helpers ----------------
__device__ __forceinline__ uint32_t smem_u32(const void* p) {
    uint32_t a;
    asm("{ .reg .u64 t; cvta.to.shared.u64 t, %1; cvt.u32.u64 %0, t; }" : "=r"(a) : "l"(p));
    return a;
}
__device__ __forceinline__ void mma_f16(float* c, const uint32_t* a, const uint32_t* b) {
    asm volatile("mma.sync.aligned.m16n8k16.row.col.f32.f16.f16.f32 "
                 "{%0,%1,%2,%3}, {%4,%5,%6,%7}, {%8,%9}, {%0,%1,%2,%3};"
                 : "+f"(c[0]), "+f"(c[1]), "+f"(c[2]), "+f"(c[3])
                 : "r"(a[0]), "r"(a[1]), "r"(a[2]), "r"(a[3]), "r"(b[0]), "r"(b[1]));
}
__device__ __forceinline__ void ldmatrix_x4(uint32_t& r0, uint32_t& r1, uint32_t& r2, uint32_t& r3,
                                            uint32_t addr) {
    asm volatile("ldmatrix.sync.aligned.m8n8.x4.shared.b16 {%0,%1,%2,%3}, [%4];"
                 : "=r"(r0), "=r"(r1), "=r"(r2), "=r"(r3) : "r"(addr));
}
__device__ __forceinline__ float fsqrt_approx(float x) {
    float r;
    asm("sqrt.approx.f32 %0, %1;" : "=f"(r) : "f"(x));
    return r;
}
#define CP_ASYNC16(dst, src) \
    asm volatile("cp.async.cg.shared.global [%0], [%1], 16;" :: "r"(dst), "l"(src) : "memory")
#define CP_COMMIT() asm volatile("cp.async.commit_group;" ::: "memory")
#define CP_WAIT(n)  asm volatile("cp.async.wait_group %0;" :: "n"(n) : "memory")

// ---------------- rope table ----------------
__global__ __launch_bounds__(256)
void rope_table_kernel()
{
    const int gid = blockIdx.x * 256 + threadIdx.x;
    const int i = gid & 31, t = gid >> 5;
    const double invf = pow(10000.0, -((double)(2 * i)) / 64.0);
    double ds, dc;
    sincos((double)t * invf, &ds, &dc);
    g_rope[gid] = make_float2((float)dc, (float)ds);
}

// ---------------- weight conversion ----------------
__global__ __launch_bounds__(256)
void wconv_kernel(const float* __restrict__ w_qkv, const float* __restrict__ w_out,
                  const float* __restrict__ w_uv, const float* __restrict__ w_mlp)
{
    const size_t gid = (size_t)blockIdx.x * 256 + threadIdx.x;
    const size_t e = gid * 4;
    const float* src;
    size_t off;
    if (e < WOFF_OUT)      { src = w_qkv; off = e; }
    else if (e < WOFF_UV)  { src = w_out; off = e - WOFF_OUT; }
    else if (e < WOFF_MLP) { src = w_uv;  off = e - WOFF_UV; }
    else                   { src = w_mlp; off = e - WOFF_MLP; }
    float4 v = *reinterpret_cast<const float4*>(src + off);
    __half2 h0 = __floats2half2_rn(v.x, v.y);
    __half2 h1 = __floats2half2_rn(v.z, v.w);
    uint2 p; p.x = *reinterpret_cast<uint32_t*>(&h0); p.y = *reinterpret_cast<uint32_t*>(&h1);
    *reinterpret_cast<uint2*>(g_wh + e) = p;
}

// ---------------- fp16 GEMM with 2-stage cp.async pipeline ----------------
// C[M,N] = A[M,K] @ W[N,K]^T (+bias)(+res). 128x128 tile, BK=32, 256 threads.
#define HP 40
#define STAGE_BYTES (128 * HP * 2)     // one tile (As or Bs) per stage = 10240 B

__global__ __launch_bounds__(256)
void tgemm_kernel(const __half* __restrict__ A, const __half* __restrict__ W,
                  const float* __restrict__ bias, const float* __restrict__ res,
                  float* __restrict__ Cf, __half* __restrict__ Ch, int M, int N, int K)
{
    __shared__ __half As[2][128][HP];
    __shared__ __half Bs[2][128][HP];
    const int tid = threadIdx.x;
    const int lane = tid & 31, warp = tid >> 5;
    const int bm = blockIdx.y * 128, bn = blockIdx.x * 128;
    const int wm = (warp & 3) * 32;
    const int wn = (warp >> 2) * 64;
    const int grp = lane >> 2, four = lane & 3;

    // cp.async row/col mapping: 512 16B-chunks per tile; tid covers 2 chunks
    const int c0r = tid >> 2,           c0c = (tid & 3) * 8;          // chunk tid
    const int c1r = (tid + 256) >> 2,   c1c = ((tid + 256) & 3) * 8;  // chunk tid+256

    const uint32_t as0 = smem_u32(&As[0][0][0]);
    const uint32_t bs0 = smem_u32(&Bs[0][0][0]);

    const uint32_t a_frag = smem_u32(&As[0][wm + (lane & 15)][(lane >> 4) * 8]);
    uint32_t b_frag[4];
#pragma unroll
    for (int ntp = 0; ntp < 4; ntp++)
        b_frag[ntp] = smem_u32(&Bs[0][wn + (2 * ntp + (lane >> 4)) * 8 + (lane & 7)][((lane >> 3) & 1) * 8]);

    float acc[2][8][4];
#pragma unroll
    for (int mi = 0; mi < 2; mi++)
#pragma unroll
        for (int ni = 0; ni < 8; ni++)
#pragma unroll
            for (int j = 0; j < 4; j++) acc[mi][ni][j] = 0.f;

    const int NC = K >> 5;

    // prefetch stage 0
    {
        CP_ASYNC16(as0 + (uint32_t)(c0r * HP + c0c) * 2, &A[(size_t)(bm + c0r) * K + c0c]);
        CP_ASYNC16(as0 + (uint32_t)(c1r * HP + c1c) * 2, &A[(size_t)(bm + c1r) * K + c1c]);
        CP_ASYNC16(bs0 + (uint32_t)(c0r * HP + c0c) * 2, &W[(size_t)(bn + c0r) * K + c0c]);
        CP_ASYNC16(bs0 + (uint32_t)(c1r * HP + c1c) * 2, &W[(size_t)(bn + c1r) * K + c1c]);
        CP_COMMIT();
    }

    for (int kc = 0; kc < NC; kc++) {
        const int p = kc & 1;
        if (kc + 1 < NC) {
            const int pn = p ^ 1;
            const int ko = (kc + 1) * 32;
            const uint32_t sa = as0 + (uint32_t)pn * STAGE_BYTES;
            const uint32_t sb = bs0 + (uint32_t)pn * STAGE_BYTES;
            CP_ASYNC16(sa + (uint32_t)(c0r * HP + c0c) * 2, &A[(size_t)(bm + c0r) * K + ko + c0c]);
            CP_ASYNC16(sa + (uint32_t)(c1r * HP + c1c) * 2, &A[(size_t)(bm + c1r) * K + ko + c1c]);
            CP_ASYNC16(sb + (uint32_t)(c0r * HP + c0c) * 2, &W[(size_t)(bn + c0r) * K + ko + c0c]);
            CP_ASYNC16(sb + (uint32_t)(c1r * HP + c1c) * 2, &W[(size_t)(bn + c1r) * K + ko + c1c]);
            CP_COMMIT();
            CP_WAIT(1);
        } else {
            CP_WAIT(0);
        }
        __syncthreads();

        const uint32_t so = (uint32_t)p * STAGE_BYTES;
#pragma unroll
        for (int ks = 0; ks < 2; ks++) {
            const uint32_t co = (uint32_t)(ks * 16) * 2;
            uint32_t af[2][4], bf[8][2];
#pragma unroll
            for (int mi = 0; mi < 2; mi++)
                ldmatrix_x4(af[mi][0], af[mi][1], af[mi][2], af[mi][3],
                            a_frag + so + (uint32_t)(mi * 16 * HP) * 2 + co);
#pragma unroll
            for (int ntp = 0; ntp < 4; ntp++)
                ldmatrix_x4(bf[2 * ntp][0], bf[2 * ntp][1], bf[2 * ntp + 1][0], bf[2 * ntp + 1][1],
                            b_frag[ntp] + so + co);
#pragma unroll
            for (int mi = 0; mi < 2; mi++)
#pragma unroll
                for (int ni = 0; ni < 8; ni++)
                    mma_f16(acc[mi][ni], af[mi], bf[ni]);
        }
        __syncthreads();   // all reads of buffer p done before it is refilled
    }

    // epilogue
#pragma unroll
    for (int mi = 0; mi < 2; mi++) {
#pragma unroll
        for (int ni = 0; ni < 8; ni++) {
            int row = bm + wm + mi * 16 + grp;
            int col = bn + wn + ni * 8 + 2 * four;
            float bx = 0.f, by = 0.f;
            if (bias) { bx = bias[col]; by = bias[col + 1]; }
#pragma unroll
            for (int half_m = 0; half_m < 2; half_m++) {
                int rr = row + half_m * 8;
                float vx = acc[mi][ni][half_m * 2 + 0] + bx;
                float vy = acc[mi][ni][half_m * 2 + 1] + by;
                if (res) {
                    float2 rv = *reinterpret_cast<const float2*>(&res[(size_t)rr * N + col]);
                    vx += rv.x; vy += rv.y;
                }
                if (Cf) {
                    float2 ov; ov.x = vx; ov.y = vy;
                    *reinterpret_cast<float2*>(&Cf[(size_t)rr * N + col]) = ov;
                } else {
                    __half2 oh = __floats2half2_rn(vx, vy);
                    *reinterpret_cast<__half2*>(&Ch[(size_t)rr * N + col]) = oh;
                }
            }
        }
    }
}

// ---------------- rmsnorm: fp32 in -> fp16 out ----------------
__global__ __launch_bounds__(256)
void rmsnorm_kernel(const float* __restrict__ x, __half* __restrict__ o)
{
    const int row = blockIdx.x;
    const float4* xr = reinterpret_cast<const float4*>(x + (size_t)row * C_);
    float4 v = xr[threadIdx.x];
    float ss = v.x * v.x + v.y * v.y + v.z * v.z + v.w * v.w;
#pragma unroll
    for (int off = 16; off > 0; off >>= 1)
        ss += __shfl_xor_sync(0xffffffffu, ss, off);
    __shared__ float red[8];
    if ((threadIdx.x & 31) == 0) red[threadIdx.x >> 5] = ss;
    __syncthreads();
    float tot = 0.f;
#pragma unroll
    for (int i = 0; i < 8; i++) tot += red[i];
    const float sc = rsqrtf(tot * (1.f / (float)C_) + 1e-6f);
    __half2 h0 = __floats2half2_rn(v.x * sc, v.y * sc);
    __half2 h1 = __floats2half2_rn(v.z * sc, v.w * sc);
    uint2 p; p.x = *reinterpret_cast<uint32_t*>(&h0); p.y = *reinterpret_cast<uint32_t*>(&h1);
    *reinterpret_cast<uint2*>(o + (size_t)row * C_ + threadIdx.x * 4) = p;
}

// ---------------- rope + transpose (table-driven) ----------------
__global__ __launch_bounds__(256)
void rope_kernel(const float* __restrict__ qkv,
                 __half* __restrict__ q, __half* __restrict__ k, __half* __restrict__ v)
{
    const int gid = blockIdx.x * 256 + threadIdx.x;
    const int i  = gid & 31;
    const int t  = (gid >> 5) & (T_ - 1);
    const int hh = (gid >> 16) & (H_ - 1);
    const int b  = gid >> 20;
    const size_t base = (size_t)(b * T_ + t) * (3 * C_) + hh * HD_;
    const float qx1 = qkv[base + i],            qx2 = qkv[base + i + 32];
    const float kx1 = qkv[base + C_ + i],       kx2 = qkv[base + C_ + i + 32];
    const float vx1 = qkv[base + 2 * C_ + i],   vx2 = qkv[base + 2 * C_ + i + 32];
    const float2 cs = g_rope[t * 32 + i];
    const float c = cs.x, s = cs.y;
    const size_t ob = ((size_t)(b * H_ + hh) * T_ + t) * HD_;
    q[ob + i]      = __float2half_rn( qx1 * c + qx2 * s);
    q[ob + i + 32] = __float2half_rn(-qx1 * s + qx2 * c);
    k[ob + i]      = __float2half_rn( kx1 * c + kx2 * s);
    k[ob + i + 32] = __float2half_rn(-kx1 * s + kx2 * c);
    v[ob + i]      = __float2half_rn(vx1);
    v[ob + i + 32] = __float2half_rn(vx2);
}

// ---------------- FA2-style fp16-mma causal hyperbolic attention ----------------
#define AP 72

struct AttnSmem3 {
    __half Qs[64][AP];
    __half Ks[64][AP];
    __half Vt[64][AP];
    float q0s[64], k0s[64];
};

extern __shared__ char attn_smem_raw[];

__global__ __launch_bounds__(128)
void attn_kernel(const __half* __restrict__ Q, const __half* __restrict__ K,
                 const __half* __restrict__ V, const float* __restrict__ curv,
                 __half* __restrict__ out)
{
    AttnSmem3& sm = *reinterpret_cast<AttnSmem3*>(attn_smem_raw);
    __half (*Ps)[AP] = sm.Qs;
    const int tid = threadIdx.x;
    const int lane = tid & 31, warp = tid >> 5;
    const int grp = lane >> 2, four = lane & 3;
    const int tq = blockIdx.x, h = blockIdx.y, b = blockIdx.z;
    const float kc = curv[h];
    const float sqkc = sqrtf(kc), ikc = 1.0f / kc;
    const size_t bhT = ((size_t)b * H_ + h) * T_;
    const int wrow = warp * 16;
    const float LOG2E = 1.4426950408889634f;

    {
        const __half* Qp = Q + (bhT + (size_t)tq * 64) * HD_;
#pragma unroll
        for (int it = 0; it < 8; it++) {
            int f = tid + it * 128;
            int r = f >> 4, dq = (f & 15) << 2;
            uint2 qv = *reinterpret_cast<const uint2*>(&Qp[r * HD_ + dq]);
            *reinterpret_cast<uint2*>(&sm.Qs[r][dq]) = qv;
        }
    }
    __syncthreads();
    if (tid < 64) {
        float ss = 0.f;
#pragma unroll 8
        for (int d = 0; d < 64; d++) { float qv = __half2float(sm.Qs[tid][d]); ss += qv * qv; }
        sm.q0s[tid] = sqrtf(kc + ss);
    }
    __syncthreads();

    const int r0 = wrow + grp, r1 = wrow + grp + 8;
    uint32_t qf[4][4];
#pragma unroll
    for (int ks = 0; ks < 4; ks++) {
        int kb = ks * 16 + 2 * four;
        qf[ks][0] = *reinterpret_cast<const uint32_t*>(&sm.Qs[r0][kb]);
        qf[ks][1] = *reinterpret_cast<const uint32_t*>(&sm.Qs[r1][kb]);
        qf[ks][2] = *reinterpret_cast<const uint32_t*>(&sm.Qs[r0][kb + 8]);
        qf[ks][3] = *reinterpret_cast<const uint32_t*>(&sm.Qs[r1][kb + 8]);
    }
    const float q0a = sm.q0s[r0];
    const float q0b = sm.q0s[r1];

    float o[8][4];
#pragma unroll
    for (int nt = 0; nt < 8; nt++)
#pragma unroll
        for (int j = 0; j < 4; j++) o[nt][j] = 0.f;
    float m0 = -1e30f, m1 = -1e30f, l0 = 0.f, l1 = 0.f;

    for (int kt = 0; kt <= tq; kt++) {
        __syncthreads();
        const __half* Kp = K + (bhT + (size_t)kt * 64) * HD_;
        const __half* Vp = V + (bhT + (size_t)kt * 64) * HD_;
#pragma unroll
        for (int it = 0; it < 8; it++) {
            int f = tid + it * 128;
            int r = f >> 4, dq = (f & 15) << 2;
            uint2 kv = *reinterpret_cast<const uint2*>(&Kp[r * HD_ + dq]);
            *reinterpret_cast<uint2*>(&sm.Ks[r][dq]) = kv;
            uint2 vv = *reinterpret_cast<const uint2*>(&Vp[r * HD_ + dq]);
            const __half* vh = reinterpret_cast<const __half*>(&vv);
            sm.Vt[dq + 0][r] = vh[0]; sm.Vt[dq + 1][r] = vh[1];
            sm.Vt[dq + 2][r] = vh[2]; sm.Vt[dq + 3][r] = vh[3];
        }
        __syncthreads();
        if (tid < 64) {
            float ss = 0.f;
#pragma unroll 8
            for (int d = 0; d < 64; d++) { float kv = __half2float(sm.Ks[tid][d]); ss += kv * kv; }
            sm.k0s[tid] = sqrtf(kc + ss);
        }
        __syncthreads();

        float s[8][4];
#pragma unroll
        for (int nt = 0; nt < 8; nt++)
#pragma unroll
            for (int j = 0; j < 4; j++) s[nt][j] = 0.f;
#pragma unroll
        for (int ks = 0; ks < 4; ks++) {
            const int kb = ks * 16 + 2 * four;
#pragma unroll
            for (int nt = 0; nt < 8; nt++) {
                uint32_t bf[2];
                bf[0] = *reinterpret_cast<const uint32_t*>(&sm.Ks[nt * 8 + grp][kb]);
                bf[1] = *reinterpret_cast<const uint32_t*>(&sm.Ks[nt * 8 + grp][kb + 8]);
                mma_f16(s[nt], qf[ks], bf);
            }
        }

        const bool diag = (kt == tq);
#pragma unroll
        for (int nt = 0; nt < 8; nt++) {
            const int c0 = nt * 8 + 2 * four;
            const float k00 = sm.k0s[c0], k01 = sm.k0s[c0 + 1];
#pragma unroll
            for (int j = 0; j < 4; j++) {
                const float q0v = (j < 2) ? q0a : q0b;
                const float k0v = (j & 1) ? k01 : k00;
                float z = (q0v * k0v - s[nt][j]) * ikc;
                z = fmaxf(z, 1.000001f);
                float w = fsqrt_approx(z * z - 1.f);
                float dis = sqkc * __logf(z + w);
                s[nt][j] = -dis;
            }
            if (diag) {
                if (c0     > r0) s[nt][0] = -1e30f;
                if (c0 + 1 > r0) s[nt][1] = -1e30f;
                if (c0     > r1) s[nt][2] = -1e30f;
                if (c0 + 1 > r1) s[nt][3] = -1e30f;
            }
        }

        float mx0 = -1e30f, mx1 = -1e30f;
#pragma unroll
        for (int nt = 0; nt < 8; nt++) {
            mx0 = fmaxf(mx0, fmaxf(s[nt][0], s[nt][1]));
            mx1 = fmaxf(mx1, fmaxf(s[nt][2], s[nt][3]));
        }
        mx0 = fmaxf(mx0, __shfl_xor_sync(0xffffffffu, mx0, 1));
        mx0 = fmaxf(mx0, __shfl_xor_sync(0xffffffffu, mx0, 2));
        mx1 = fmaxf(mx1, __shfl_xor_sync(0xffffffffu, mx1, 1));
        mx1 = fmaxf(mx1, __shfl_xor_sync(0xffffffffu, mx1, 2));
        const float nm0 = fmaxf(m0, mx0), nm1 = fmaxf(m1, mx1);
        const float a0 = __expf(m0 - nm0), a1 = __expf(m1 - nm1);
        float rs0 = 0.f, rs1 = 0.f;
        __half2 ph[8][2];
#pragma unroll
        for (int nt = 0; nt < 8; nt++) {
            float p0 = exp2f((s[nt][0] - nm0) * LOG2E);
            float p1 = exp2f((s[nt][1] - nm0) * LOG2E);
            float p2 = exp2f((s[nt][2] - nm1) * LOG2E);
            float p3 = exp2f((s[nt][3] - nm1) * LOG2E);
            ph[nt][0] = __floats2half2_rn(p0, p1);
            ph[nt][1] = __floats2half2_rn(p2, p3);
            float2 f0 = __half22float2(ph[nt][0]);
            float2 f1 = __half22float2(ph[nt][1]);
            rs0 += f0.x + f0.y; rs1 += f1.x + f1.y;
        }
        rs0 += __shfl_xor_sync(0xffffffffu, rs0, 1);
        rs0 += __shfl_xor_sync(0xffffffffu, rs0, 2);
        rs1 += __shfl_xor_sync(0xffffffffu, rs1, 1);
        rs1 += __shfl_xor_sync(0xffffffffu, rs1, 2);
        l0 = l0 * a0 + rs0; l1 = l1 * a1 + rs1;
        m0 = nm0; m1 = nm1;

#pragma unroll
        for (int nt = 0; nt < 8; nt++) {
            o[nt][0] *= a0; o[nt][1] *= a0; o[nt][2] *= a1; o[nt][3] *= a1;
            const int c0 = nt * 8 + 2 * four;
            *reinterpret_cast<__half2*>(&Ps[r0][c0]) = ph[nt][0];
            *reinterpret_cast<__half2*>(&Ps[r1][c0]) = ph[nt][1];
        }
        __syncwarp();

#pragma unroll
        for (int ks = 0; ks < 4; ks++) {
            const int kb = ks * 16 + 2 * four;
            uint32_t af[4];
            af[0] = *reinterpret_cast<const uint32_t*>(&Ps[r0][kb]);
            af[1] = *reinterpret_cast<const uint32_t*>(&Ps[r1][kb]);
            af[2] = *reinterpret_cast<const uint32_t*>(&Ps[r0][kb + 8]);
            af[3] = *reinterpret_cast<const uint32_t*>(&Ps[r1][kb + 8]);
#pragma unroll
            for (int nt = 0; nt < 8; nt++) {
                uint32_t bf[2];
                bf[0] = *reinterpret_cast<const uint32_t*>(&sm.Vt[nt * 8 + grp][kb]);
                bf[1] = *reinterpret_cast<const uint32_t*>(&sm.Vt[nt * 8 + grp][kb + 8]);
                mma_f16(o[nt], af, bf);
            }
        }
    }

    const float inv0 = 1.f / l0, inv1 = 1.f / l1;
    const int gr0 = tq * 64 + r0, gr1 = tq * 64 + r1;
#pragma unroll
    for (int nt = 0; nt < 8; nt++) {
        const int d0 = nt * 8 + 2 * four;
        __half2 ov;
        ov = __floats2half2_rn(o[nt][0] * inv0, o[nt][1] * inv0);
        *reinterpret_cast<__half2*>(&out[(((size_t)b * T_ + gr0) * H_ + h) * HD_ + d0]) = ov;
        ov = __floats2half2_rn(o[nt][2] * inv1, o[nt][3] * inv1);
        *reinterpret_cast<__half2*>(&out[(((size_t)b * T_ + gr1) * H_ + h) * HD_ + d0]) = ov;
    }
}

// ---------------- gating: g = u * silu(vg), fp16 ----------------
__global__ __launch_bounds__(256)
void gate_kernel(const __half* __restrict__ uv, __half* __restrict__ g)
{
    const size_t gid = (size_t)blockIdx.x * 256 + threadIdx.x;
    const size_t row = gid >> 10;
    const size_t c4 = gid & 1023;
    uint2 pu = *reinterpret_cast<const uint2*>(uv + row * (8 * (size_t)C_) + c4 * 4);
    uint2 pv = *reinterpret_cast<const uint2*>(uv + row * (8 * (size_t)C_) + 4 * C_ + c4 * 4);
    const __half* uh = reinterpret_cast<const __half*>(&pu);
    const __half* vh = reinterpret_cast<const __half*>(&pv);
    __half rh[4];
#pragma unroll
    for (int j = 0; j < 4; j++) {
        float u = __half2float(uh[j]);
        float vg = __half2float(vh[j]);
        rh[j] = __float2half_rn(u * vg / (1.f + __expf(-vg)));
    }
    *reinterpret_cast<uint2*>(g + gid * 4) = *reinterpret_cast<uint2*>(rh);
}

// ---------------- launch ----------------
extern "C" void kernel_launch(void* const* d_in, const int* in_sizes, int n_in,
                              void* d_out, int out_size)
{
    const float* x      = (const float*)d_in[0];
    const float* w_qkv  = (const float*)d_in[1];
    const float* w_out  = (const float*)d_in[2];
    const float* curv   = (const float*)d_in[3];
    const float* w_uv   = (const float*)d_in[4];
    const float* b_uv   = (const float*)d_in[5];
    const float* w_mlp  = (const float*)d_in[6];
    const float* b_mlp  = (const float*)d_in[7];
    float* out = (float*)d_out;

    float *qkv, *x1;
    __half *hh, *wh, *qh, *kh, *vh, *attnh, *uvh, *gatedh;
    cudaGetSymbolAddress((void**)&qkv, g_qkv);
    cudaGetSymbolAddress((void**)&x1, g_x1);
    cudaGetSymbolAddress((void**)&hh, g_hh);
    cudaGetSymbolAddress((void**)&wh, g_wh);
    cudaGetSymbolAddress((void**)&qh, g_qh);
    cudaGetSymbolAddress((void**)&kh, g_kh);
    cudaGetSymbolAddress((void**)&vh, g_vh);
    cudaGetSymbolAddress((void**)&attnh, g_attnh);
    cudaGetSymbolAddress((void**)&uvh, g_uvh);
    cudaGetSymbolAddress((void**)&gatedh, g_gatedh);

    const int attn_smem = (int)sizeof(AttnSmem3);
    cudaFuncSetAttribute(attn_kernel, cudaFuncAttributeMaxDynamicSharedMemorySize, attn_smem);

    // 0a) rope table
    rope_table_kernel<<<(T_ * 32) / 256, 256>>>();
    // 0b) weights -> fp16
    wconv_kernel<<<(16 * C_ * C_ / 4) / 256, 256>>>(w_qkv, w_out, w_uv, w_mlp);
    // 1) h = rmsnorm(x)
    rmsnorm_kernel<<<M_, 256>>>(x, hh);
    // 2) qkv = h @ w_qkv^T
    tgemm_kernel<<<dim3(3 * C_ / 128, M_ / 128), 256>>>(hh, wh + WOFF_QKV, nullptr, nullptr, qkv, nullptr, M_, 3 * C_, C_);
    // 3) rope
    rope_kernel<<<(B_ * H_ * T_ * 32) / 256, 256>>>(qkv, qh, kh, vh);
    // 4) attention
    attn_kernel<<<dim3(T_ / 64, H_, B_), 128, attn_smem>>>(qh, kh, vh, curv, attnh);
    // 5) x1 = x + attn @ w_out^T
    tgemm_kernel<<<dim3(C_ / 128, M_ / 128), 256>>>(attnh, wh + WOFF_OUT, nullptr, x, x1, nullptr, M_, C_, C_);
    // 6) h = rmsnorm(x1)
    rmsnorm_kernel<<<M_, 256>>>(x1, hh);
    // 7) uv = h @ w_uv^T + b_uv
    tgemm_kernel<<<dim3(8 * C_ / 128, M_ / 128), 256>>>(hh, wh + WOFF_UV, b_uv, nullptr, nullptr, uvh, M_, 8 * C_, C_);
    // 8) gated = u * silu(vg)
    gate_kernel<<<(M_ * 4 * C_ / 4) / 256, 256>>>(uvh, gatedh);
    // 9) out = x1 + gated @ w_mlp^T + b_mlp
    tgemm_kernel<<<dim3(C_ / 128, M_ / 128), 256>>>(gatedh, wh + WOFF_MLP, b_mlp, x1, out, nullptr, M_, C_, 4 * C_);
}